// round 1
// baseline (speedup 1.0000x reference)
#include <cuda_runtime.h>
#include <cuda_bf16.h>
#include <math.h>

#define NROWS 8192
#define H 512
#define CC 100
#define RR 69
#define PP 69
#define EPSV 1e-8f

// ---------------- scratch (device globals, no runtime alloc) ----------------
__device__ float g_vcat[(size_t)NROWS * 3 * H];   // concat(s,p,o)  N x 1536
__device__ float g_h[(size_t)NROWS * H];          // hidden 1
__device__ float g_vf[(size_t)NROWS * H];         // hidden 2 (vf)
__device__ float g_rf[(size_t)NROWS * 2 * H];     // [vf | attended] N x 1024
__device__ float g_h2[(size_t)NROWS * H];         // hidden 3

// ---------------- concat kernel ----------------
__global__ void concat_kernel(const float* __restrict__ s,
                              const float* __restrict__ p,
                              const float* __restrict__ o) {
    // copy as float4; layout: row n has [s(512) | p(512) | o(512)]
    size_t idx = (size_t)blockIdx.x * blockDim.x + threadIdx.x;   // float4 index
    size_t total = (size_t)NROWS * 3 * H / 4;
    if (idx >= total) return;
    size_t row = idx / (3 * H / 4);
    size_t col4 = idx % (3 * H / 4);          // 0..383
    const float4* src;
    size_t within;
    if (col4 < H / 4)            { src = (const float4*)s; within = col4; }
    else if (col4 < 2 * (H / 4)) { src = (const float4*)p; within = col4 - H / 4; }
    else                         { src = (const float4*)o; within = col4 - 2 * (H / 4); }
    float4 v = src[row * (H / 4) + within];
    ((float4*)g_vcat)[idx] = v;
}

// ---------------- SGEMM 128x128x8, 256 threads, 8x8 per thread ----------------
// C[M,Nd] = act(A[M,Kd] @ B[Kd,Nd] + bias[Nd]);  M % 128 == 0, Kd % 8 == 0.
template<bool RELU>
__global__ __launch_bounds__(256)
void sgemm_kernel(const float* __restrict__ A, const float* __restrict__ B,
                  const float* __restrict__ bias, float* __restrict__ C,
                  int M, int Kd, int Nd) {
    __shared__ float As[8][132];
    __shared__ float Bs[8][128];

    const int bm = blockIdx.y * 128;
    const int bn = blockIdx.x * 128;
    const int tid = threadIdx.x;

    const int arow = tid >> 1;            // 0..127
    const int acol = (tid & 1) * 4;       // 0 or 4
    const int brow = tid >> 5;            // 0..7
    const int bcol = (tid & 31) * 4;      // 0..124

    const int tx = tid & 15;              // col group
    const int ty = tid >> 4;              // row group

    float acc[8][8];
#pragma unroll
    for (int i = 0; i < 8; i++)
#pragma unroll
        for (int j = 0; j < 8; j++) acc[i][j] = 0.f;

    const bool full_n = (bn + 128 <= Nd);

    for (int k0 = 0; k0 < Kd; k0 += 8) {
        // A tile (always full: M%128==0, Kd%8==0)
        float4 a4 = *(const float4*)(A + (size_t)(bm + arow) * Kd + k0 + acol);
        As[acol + 0][arow] = a4.x;
        As[acol + 1][arow] = a4.y;
        As[acol + 2][arow] = a4.z;
        As[acol + 3][arow] = a4.w;
        // B tile
        if (full_n) {
            float4 b4 = *(const float4*)(B + (size_t)(k0 + brow) * Nd + bn + bcol);
            *(float4*)&Bs[brow][bcol] = b4;
        } else {
#pragma unroll
            for (int c = 0; c < 4; c++) {
                int col = bn + bcol + c;
                Bs[brow][bcol + c] = (col < Nd) ? B[(size_t)(k0 + brow) * Nd + col] : 0.f;
            }
        }
        __syncthreads();

#pragma unroll
        for (int k = 0; k < 8; k++) {
            float ar[8], br[8];
            *(float4*)&ar[0] = *(const float4*)&As[k][ty * 8];
            *(float4*)&ar[4] = *(const float4*)&As[k][ty * 8 + 4];
            *(float4*)&br[0] = *(const float4*)&Bs[k][tx * 8];
            *(float4*)&br[4] = *(const float4*)&Bs[k][tx * 8 + 4];
#pragma unroll
            for (int i = 0; i < 8; i++)
#pragma unroll
                for (int j = 0; j < 8; j++)
                    acc[i][j] = fmaf(ar[i], br[j], acc[i][j]);
        }
        __syncthreads();
    }

    // epilogue
#pragma unroll
    for (int i = 0; i < 8; i++) {
        int row = bm + ty * 8 + i;
        float* crow = C + (size_t)row * Nd;
#pragma unroll
        for (int j = 0; j < 8; j++) {
            int col = bn + tx * 8 + j;
            if (col < Nd) {
                float v = acc[i][j] + bias[col];
                if (RELU) v = fmaxf(v, 0.f);
                crow[col] = v;
            }
        }
    }
}

// ---------------- fused attention: gather + cos + softmax + attended ----------------
// one CTA per row n; rel tile (69 x 512 floats) cached in SMEM, read from HBM once.
// writes rf[n] = [vf(512) | attended(512)]
__global__ __launch_bounds__(512)
void attn_kernel(const float* __restrict__ vf,
                 const float* __restrict__ rel_base,
                 const int* __restrict__ scats,
                 const int* __restrict__ ocats,
                 float* __restrict__ rf) {
    extern __shared__ float sm[];
    float* srel  = sm;                    // RR*H
    float* svf   = srel + RR * H;         // H
    float* sdot  = svf + H;               // RR
    float* ssq   = sdot + RR;             // RR
    float* sattn = ssq + RR;              // RR

    const int n = blockIdx.x;
    const int tid = threadIdx.x;
    const int lane = tid & 31;
    const int warp = tid >> 5;
    const int nwarps = blockDim.x >> 5;

    // load vf row into smem
    const float4* vfn = (const float4*)(vf + (size_t)n * H);
    for (int j = tid; j < H / 4; j += blockDim.x)
        ((float4*)svf)[j] = vfn[j];
    __syncthreads();

    const long s = scats[n];
    const long o = ocats[n];

    // gather rel rows: warp w handles r = w, w+nwarps, ...
    for (int r = warp; r < RR; r += nwarps) {
        const float4* src = (const float4*)(rel_base + (((size_t)s * RR + r) * CC + o) * H);
        float4* dst = (float4*)(srel + (size_t)r * H);
        float dot = 0.f, sq = 0.f;
#pragma unroll
        for (int it = 0; it < H / 4 / 32; it++) {        // 4 iterations
            int j = lane + it * 32;
            float4 x = src[j];
            dst[j] = x;
            float4 v4 = ((const float4*)svf)[j];
            dot += x.x * v4.x + x.y * v4.y + x.z * v4.z + x.w * v4.w;
            sq  += x.x * x.x + x.y * x.y + x.z * x.z + x.w * x.w;
        }
#pragma unroll
        for (int off = 16; off > 0; off >>= 1) {
            dot += __shfl_down_sync(0xffffffffu, dot, off);
            sq  += __shfl_down_sync(0xffffffffu, sq, off);
        }
        if (lane == 0) { sdot[r] = dot; ssq[r] = sq; }
    }
    __syncthreads();

    // warp 0: vn + cos + softmax
    if (warp == 0) {
        float vsq = 0.f;
        for (int j = lane; j < H; j += 32) { float v = svf[j]; vsq += v * v; }
#pragma unroll
        for (int off = 16; off > 0; off >>= 1)
            vsq += __shfl_xor_sync(0xffffffffu, vsq, off);
        float vn = sqrtf(vsq);

        float c[3];
#pragma unroll
        for (int t = 0; t < 3; t++) {
            int r = lane + 32 * t;
            c[t] = (r < RR) ? sdot[r] / fmaxf(vn * sqrtf(ssq[r]), EPSV) : -1e30f;
        }
        float m = fmaxf(fmaxf(c[0], c[1]), c[2]);
#pragma unroll
        for (int off = 16; off > 0; off >>= 1)
            m = fmaxf(m, __shfl_xor_sync(0xffffffffu, m, off));
        float e[3], esum = 0.f;
#pragma unroll
        for (int t = 0; t < 3; t++) {
            int r = lane + 32 * t;
            e[t] = (r < RR) ? __expf(c[t] - m) : 0.f;
            esum += e[t];
        }
#pragma unroll
        for (int off = 16; off > 0; off >>= 1)
            esum += __shfl_xor_sync(0xffffffffu, esum, off);
        float inv = 1.f / esum;
#pragma unroll
        for (int t = 0; t < 3; t++) {
            int r = lane + 32 * t;
            if (r < RR) sattn[r] = e[t] * inv;
        }
    }
    __syncthreads();

    // attended + write rf
    float* rfn = rf + (size_t)n * 2 * H;
    for (int d = tid; d < H; d += blockDim.x) {
        float acc = 0.f;
#pragma unroll 8
        for (int r = 0; r < RR; r++)
            acc = fmaf(sattn[r], srel[(size_t)r * H + d], acc);
        rfn[H + d] = acc;
        rfn[d] = svf[d];
    }
}

// ---------------- launch ----------------
extern "C" void kernel_launch(void* const* d_in, const int* in_sizes, int n_in,
                              void* d_out, int out_size) {
    const float* sfeat = (const float*)d_in[0];
    const float* pfeat = (const float*)d_in[1];
    const float* ofeat = (const float*)d_in[2];
    const float* rel   = (const float*)d_in[3];
    const float* w1    = (const float*)d_in[4];
    const float* b1    = (const float*)d_in[5];
    const float* w2    = (const float*)d_in[6];
    const float* b2    = (const float*)d_in[7];
    const float* rw1   = (const float*)d_in[8];
    const float* rb1   = (const float*)d_in[9];
    const float* rw2   = (const float*)d_in[10];
    const float* rb2   = (const float*)d_in[11];
    const int*   scats = (const int*)d_in[12];
    const int*   ocats = (const int*)d_in[13];
    float* out = (float*)d_out;

    float *p_vcat, *p_h, *p_vf, *p_rf, *p_h2;
    cudaGetSymbolAddress((void**)&p_vcat, g_vcat);
    cudaGetSymbolAddress((void**)&p_h,    g_h);
    cudaGetSymbolAddress((void**)&p_vf,   g_vf);
    cudaGetSymbolAddress((void**)&p_rf,   g_rf);
    cudaGetSymbolAddress((void**)&p_h2,   g_h2);

    // 1) concat
    {
        size_t total4 = (size_t)NROWS * 3 * H / 4;
        int threads = 256;
        int blocks = (int)((total4 + threads - 1) / threads);
        concat_kernel<<<blocks, threads>>>(sfeat, pfeat, ofeat);
    }
    // 2) h = relu(vcat @ w1 + b1)   (8192 x 512, K=1536)
    {
        dim3 grid(512 / 128, NROWS / 128);
        sgemm_kernel<true><<<grid, 256>>>(p_vcat, w1, b1, p_h, NROWS, 3 * H, H);
    }
    // 3) vf = relu(h @ w2 + b2)
    {
        dim3 grid(512 / 128, NROWS / 128);
        sgemm_kernel<true><<<grid, 256>>>(p_h, w2, b2, p_vf, NROWS, H, H);
    }
    // 4) attention -> rf = [vf | attended]
    {
        int smem_bytes = (RR * H + H + 3 * RR) * (int)sizeof(float);
        cudaFuncSetAttribute(attn_kernel, cudaFuncAttributeMaxDynamicSharedMemorySize, smem_bytes);
        attn_kernel<<<NROWS, 512, smem_bytes>>>(p_vf, rel, scats, ocats, p_rf);
    }
    // 5) h2 = relu(rf @ rw1 + rb1)  (K=1024)
    {
        dim3 grid(512 / 128, NROWS / 128);
        sgemm_kernel<true><<<grid, 256>>>(p_rf, rw1, rb1, p_h2, NROWS, 2 * H, H);
    }
    // 6) plogits = h2 @ rw2 + rb2   (Nd=69)
    {
        dim3 grid(1, NROWS / 128);
        sgemm_kernel<false><<<grid, 256>>>(p_h2, rw2, rb2, out, NROWS, H, PP);
    }
}

// round 2
// speedup vs baseline: 1.2925x; 1.2925x over previous
#include <cuda_runtime.h>
#include <cuda_bf16.h>
#include <math.h>

#define NROWS 8192
#define H 512
#define CC 100
#define RR 69
#define PP 69
#define EPSV 1e-8f

typedef unsigned long long ull;

// ---------------- scratch (device globals, no runtime alloc) ----------------
__device__ float g_vcat[(size_t)NROWS * 3 * H];   // concat(s,p,o)  N x 1536
__device__ float g_h[(size_t)NROWS * H];          // hidden 1
__device__ float g_vf[(size_t)NROWS * H];         // hidden 2 (vf)
__device__ float g_rf[(size_t)NROWS * 2 * H];     // [vf | attended] N x 1024
__device__ float g_h2[(size_t)NROWS * H];         // hidden 3

// ---------------- helpers ----------------
__device__ __forceinline__ ull pack2(float lo, float hi) {
    ull r; asm("mov.b64 %0, {%1, %2};" : "=l"(r) : "f"(lo), "f"(hi)); return r;
}
__device__ __forceinline__ void unpack2(ull v, float& lo, float& hi) {
    asm("mov.b64 {%0, %1}, %2;" : "=f"(lo), "=f"(hi) : "l"(v));
}
__device__ __forceinline__ void fma2(ull& d, ull a, ull b) {
    asm("fma.rn.f32x2 %0, %1, %2, %3;" : "=l"(d) : "l"(a), "l"(b), "l"(d));
}
__device__ __forceinline__ void cp_async16(void* smem_dst, const void* gmem_src) {
    unsigned saddr = (unsigned)__cvta_generic_to_shared(smem_dst);
    asm volatile("cp.async.cg.shared.global [%0], [%1], 16;" :: "r"(saddr), "l"(gmem_src) : "memory");
}
__device__ __forceinline__ void cp_commit() {
    asm volatile("cp.async.commit_group;" ::: "memory");
}
__device__ __forceinline__ void cp_wait_dyn(int rem) {
    switch (rem) {
        case 0: asm volatile("cp.async.wait_group 0;" ::: "memory"); break;
        case 1: asm volatile("cp.async.wait_group 1;" ::: "memory"); break;
        case 2: asm volatile("cp.async.wait_group 2;" ::: "memory"); break;
        case 3: asm volatile("cp.async.wait_group 3;" ::: "memory"); break;
        default: asm volatile("cp.async.wait_group 4;" ::: "memory"); break;
    }
}

// ---------------- concat kernel ----------------
__global__ void concat_kernel(const float* __restrict__ s,
                              const float* __restrict__ p,
                              const float* __restrict__ o) {
    size_t idx = (size_t)blockIdx.x * blockDim.x + threadIdx.x;   // float4 index
    size_t total = (size_t)NROWS * 3 * H / 4;
    if (idx >= total) return;
    size_t row = idx / (3 * H / 4);
    size_t col4 = idx % (3 * H / 4);
    const float4* src;
    size_t within;
    if (col4 < H / 4)            { src = (const float4*)s; within = col4; }
    else if (col4 < 2 * (H / 4)) { src = (const float4*)p; within = col4 - H / 4; }
    else                         { src = (const float4*)o; within = col4 - 2 * (H / 4); }
    ((float4*)g_vcat)[idx] = src[row * (H / 4) + within];
}

// ---------------- SGEMM 128x128x8, 256 threads, FFMA2 packed math ----------------
// Per thread: 4 row-pairs x 8 cols of packed f32x2 accumulators (8x8 scalar tile).
template<bool RELU>
__global__ __launch_bounds__(256)
void sgemm_kernel(const float* __restrict__ A, const float* __restrict__ B,
                  const float* __restrict__ bias, float* __restrict__ C,
                  int M, int Kd, int Nd) {
    __shared__ float As[8][132];   // [k][m], row stride 132*4=528B (16B aligned)
    __shared__ float Bs[8][128];   // [k][n]

    const int bm = blockIdx.y * 128;
    const int bn = blockIdx.x * 128;
    const int tid = threadIdx.x;

    const int arow = tid >> 1;            // 0..127
    const int acol = (tid & 1) * 4;       // 0 or 4
    const int brow = tid >> 5;            // 0..7
    const int bcol = (tid & 31) * 4;      // 0..124

    const int tx = tid & 15;              // col group (8 cols)
    const int ty = tid >> 4;              // row group (8 rows)

    ull acc2[4][8];
#pragma unroll
    for (int i = 0; i < 4; i++)
#pragma unroll
        for (int j = 0; j < 8; j++) acc2[i][j] = 0ull;

    const bool full_n = (bn + 128 <= Nd);

    for (int k0 = 0; k0 < Kd; k0 += 8) {
        float4 a4 = *(const float4*)(A + (size_t)(bm + arow) * Kd + k0 + acol);
        As[acol + 0][arow] = a4.x;
        As[acol + 1][arow] = a4.y;
        As[acol + 2][arow] = a4.z;
        As[acol + 3][arow] = a4.w;
        if (full_n) {
            *(float4*)&Bs[brow][bcol] =
                *(const float4*)(B + (size_t)(k0 + brow) * Nd + bn + bcol);
        } else {
#pragma unroll
            for (int c = 0; c < 4; c++) {
                int col = bn + bcol + c;
                Bs[brow][bcol + c] = (col < Nd) ? B[(size_t)(k0 + brow) * Nd + col] : 0.f;
            }
        }
        __syncthreads();

#pragma unroll
        for (int k = 0; k < 8; k++) {
            // A row-pairs: natively packed pairs from SMEM
            ulonglong2 av0 = *(const ulonglong2*)&As[k][ty * 8];       // pairs (0,1),(2,3)
            ulonglong2 av1 = *(const ulonglong2*)&As[k][ty * 8 + 4];   // pairs (4,5),(6,7)
            ull a2[4] = {av0.x, av0.y, av1.x, av1.y};
            float4 blo = *(const float4*)&Bs[k][tx * 8];
            float4 bhi = *(const float4*)&Bs[k][tx * 8 + 4];
            ull b2[8];
            b2[0] = pack2(blo.x, blo.x); b2[1] = pack2(blo.y, blo.y);
            b2[2] = pack2(blo.z, blo.z); b2[3] = pack2(blo.w, blo.w);
            b2[4] = pack2(bhi.x, bhi.x); b2[5] = pack2(bhi.y, bhi.y);
            b2[6] = pack2(bhi.z, bhi.z); b2[7] = pack2(bhi.w, bhi.w);
#pragma unroll
            for (int i = 0; i < 4; i++)
#pragma unroll
                for (int j = 0; j < 8; j++)
                    fma2(acc2[i][j], a2[i], b2[j]);
        }
        __syncthreads();
    }

    // epilogue
#pragma unroll
    for (int i = 0; i < 4; i++) {
        int row_lo = bm + ty * 8 + 2 * i;
        float* c0 = C + (size_t)row_lo * Nd;
        float* c1 = C + (size_t)(row_lo + 1) * Nd;
#pragma unroll
        for (int j = 0; j < 8; j++) {
            int col = bn + tx * 8 + j;
            if (col < Nd) {
                float lo, hi;
                unpack2(acc2[i][j], lo, hi);
                float bv = bias[col];
                lo += bv; hi += bv;
                if (RELU) { lo = fmaxf(lo, 0.f); hi = fmaxf(hi, 0.f); }
                c0[col] = lo;
                c1[col] = hi;
            }
        }
    }
}

// ---------------- fused attention (cp.async pipelined) ----------------
// one CTA per row n; rel tile (69 x 512 f32) streamed into SMEM via cp.async,
// dot/sq pipelined against in-flight commit groups; vf kept in registers.
__global__ __launch_bounds__(512)
void attn_kernel(const float* __restrict__ vf,
                 const float* __restrict__ rel_base,
                 const int* __restrict__ scats,
                 const int* __restrict__ ocats,
                 float* __restrict__ rf) {
    extern __shared__ float sm[];
    float* srel  = sm;                    // RR*H
    float* sdot  = srel + RR * H;         // RR
    float* ssq   = sdot + RR;             // RR
    float* sattn = ssq + RR;              // RR

    const int n = blockIdx.x;
    const int tid = threadIdx.x;
    const int lane = tid & 31;
    const int warp = tid >> 5;

    const int s = scats[n];
    const int o = ocats[n];
    const float* relp = rel_base + (((size_t)s * RR) * CC + o) * H;  // + r*CC*H per row

    // vf chunks for this lane: j = lane + 32*it  (float4 index), covers all 512 per warp
    float4 vf4[4];
    const float4* vfn = (const float4*)(vf + (size_t)n * H);
#pragma unroll
    for (int it = 0; it < 4; it++) vf4[it] = __ldg(&vfn[lane + 32 * it]);

    // issue all rel row loads: warp w owns rows r = w + 16*t
    const int T = (warp < (RR & 15)) ? (RR / 16 + 1) : (RR / 16);   // 5 or 4
    for (int t = 0; t < T; t++) {
        int r = warp + 16 * t;
        const float* src = relp + (size_t)r * CC * H;
        float* dst = srel + (size_t)r * H;
#pragma unroll
        for (int it = 0; it < 4; it++) {
            int j = lane + 32 * it;
            cp_async16(dst + 4 * j, src + 4 * j);
        }
        cp_commit();
    }

    // pipelined dot/sq per row
    for (int t = 0; t < T; t++) {
        cp_wait_dyn(T - 1 - t);
        __syncwarp();
        int r = warp + 16 * t;
        const float4* rr4 = (const float4*)(srel + (size_t)r * H);
        float dot = 0.f, sq = 0.f;
#pragma unroll
        for (int it = 0; it < 4; it++) {
            float4 x = rr4[lane + 32 * it];
            float4 v = vf4[it];
            dot += x.x * v.x + x.y * v.y + x.z * v.z + x.w * v.w;
            sq  += x.x * x.x + x.y * x.y + x.z * x.z + x.w * x.w;
        }
#pragma unroll
        for (int off = 16; off > 0; off >>= 1) {
            dot += __shfl_down_sync(0xffffffffu, dot, off);
            sq  += __shfl_down_sync(0xffffffffu, sq, off);
        }
        if (lane == 0) { sdot[r] = dot; ssq[r] = sq; }
    }
    __syncthreads();

    // warp 0: ||vf|| + cos + softmax
    if (warp == 0) {
        float vsq = 0.f;
#pragma unroll
        for (int it = 0; it < 4; it++) {
            float4 v = vf4[it];
            vsq += v.x * v.x + v.y * v.y + v.z * v.z + v.w * v.w;
        }
#pragma unroll
        for (int off = 16; off > 0; off >>= 1)
            vsq += __shfl_xor_sync(0xffffffffu, vsq, off);
        float vn = sqrtf(vsq);

        float c[3];
#pragma unroll
        for (int t = 0; t < 3; t++) {
            int r = lane + 32 * t;
            c[t] = (r < RR) ? sdot[r] / fmaxf(vn * sqrtf(ssq[r]), EPSV) : -1e30f;
        }
        float m = fmaxf(fmaxf(c[0], c[1]), c[2]);
#pragma unroll
        for (int off = 16; off > 0; off >>= 1)
            m = fmaxf(m, __shfl_xor_sync(0xffffffffu, m, off));
        float e[3], esum = 0.f;
#pragma unroll
        for (int t = 0; t < 3; t++) {
            int r = lane + 32 * t;
            e[t] = (r < RR) ? __expf(c[t] - m) : 0.f;
            esum += e[t];
        }
#pragma unroll
        for (int off = 16; off > 0; off >>= 1)
            esum += __shfl_xor_sync(0xffffffffu, esum, off);
        float inv = 1.f / esum;
#pragma unroll
        for (int t = 0; t < 3; t++) {
            int r = lane + 32 * t;
            if (r < RR) sattn[r] = e[t] * inv;
        }
    }
    __syncthreads();

    // attended + write rf = [vf | attended]
    float* rfn = rf + (size_t)n * 2 * H;
    {
        int d = tid;  // 512 threads, 512 dims
        float acc = 0.f;
#pragma unroll 8
        for (int r = 0; r < RR; r++)
            acc = fmaf(sattn[r], srel[(size_t)r * H + d], acc);
        rfn[H + d] = acc;
        rfn[d] = __ldg(vf + (size_t)n * H + d);
    }
}

// ---------------- launch ----------------
extern "C" void kernel_launch(void* const* d_in, const int* in_sizes, int n_in,
                              void* d_out, int out_size) {
    const float* sfeat = (const float*)d_in[0];
    const float* pfeat = (const float*)d_in[1];
    const float* ofeat = (const float*)d_in[2];
    const float* rel   = (const float*)d_in[3];
    const float* w1    = (const float*)d_in[4];
    const float* b1    = (const float*)d_in[5];
    const float* w2    = (const float*)d_in[6];
    const float* b2    = (const float*)d_in[7];
    const float* rw1   = (const float*)d_in[8];
    const float* rb1   = (const float*)d_in[9];
    const float* rw2   = (const float*)d_in[10];
    const float* rb2   = (const float*)d_in[11];
    const int*   scats = (const int*)d_in[12];
    const int*   ocats = (const int*)d_in[13];
    float* out = (float*)d_out;

    float *p_vcat, *p_h, *p_vf, *p_rf, *p_h2;
    cudaGetSymbolAddress((void**)&p_vcat, g_vcat);
    cudaGetSymbolAddress((void**)&p_h,    g_h);
    cudaGetSymbolAddress((void**)&p_vf,   g_vf);
    cudaGetSymbolAddress((void**)&p_rf,   g_rf);
    cudaGetSymbolAddress((void**)&p_h2,   g_h2);

    // 1) concat
    {
        size_t total4 = (size_t)NROWS * 3 * H / 4;
        int threads = 256;
        int blocks = (int)((total4 + threads - 1) / threads);
        concat_kernel<<<blocks, threads>>>(sfeat, pfeat, ofeat);
    }
    // 2) h = relu(vcat @ w1 + b1)
    {
        dim3 grid(512 / 128, NROWS / 128);
        sgemm_kernel<true><<<grid, 256>>>(p_vcat, w1, b1, p_h, NROWS, 3 * H, H);
    }
    // 3) vf = relu(h @ w2 + b2)
    {
        dim3 grid(512 / 128, NROWS / 128);
        sgemm_kernel<true><<<grid, 256>>>(p_h, w2, b2, p_vf, NROWS, H, H);
    }
    // 4) attention -> rf = [vf | attended]
    {
        int smem_bytes = (RR * H + 3 * RR) * (int)sizeof(float);
        cudaFuncSetAttribute(attn_kernel, cudaFuncAttributeMaxDynamicSharedMemorySize, smem_bytes);
        attn_kernel<<<NROWS, 512, smem_bytes>>>(p_vf, rel, scats, ocats, p_rf);
    }
    // 5) h2 = relu(rf @ rw1 + rb1)
    {
        dim3 grid(512 / 128, NROWS / 128);
        sgemm_kernel<true><<<grid, 256>>>(p_rf, rw1, rb1, p_h2, NROWS, 2 * H, H);
    }
    // 6) plogits = h2 @ rw2 + rb2
    {
        dim3 grid(1, NROWS / 128);
        sgemm_kernel<false><<<grid, 256>>>(p_h2, rw2, rb2, out, NROWS, H, PP);
    }
}

// round 5
// speedup vs baseline: 1.9965x; 1.5447x over previous
#include <cuda_runtime.h>
#include <cuda_bf16.h>
#include <math.h>
#include <stdint.h>
#include <string.h>

#define NROWS 8192
#define H 512
#define CC 100
#define RR 69
#define PP 69
#define EPSV 1e-8f

typedef unsigned long long ull;

// ---------------- scratch (device globals, no runtime alloc) ----------------
__device__ __nv_bfloat16 g_vcat_hi[(size_t)NROWS * 3 * H];
__device__ __nv_bfloat16 g_vcat_lo[(size_t)NROWS * 3 * H];
__device__ __nv_bfloat16 g_h_hi[(size_t)NROWS * H];
__device__ __nv_bfloat16 g_h_lo[(size_t)NROWS * H];
__device__ float         g_vf[(size_t)NROWS * H];      // f32 vf for attn
__device__ __nv_bfloat16 g_rf_hi[(size_t)NROWS * 2 * H];
__device__ __nv_bfloat16 g_rf_lo[(size_t)NROWS * 2 * H];
__device__ float         g_h2[(size_t)NROWS * H];      // f32 h2 for final FFMA GEMM
// transposed weights (N x K), bf16 hi/lo
__device__ __nv_bfloat16 g_w1t_hi[(size_t)H * 3 * H];
__device__ __nv_bfloat16 g_w1t_lo[(size_t)H * 3 * H];
__device__ __nv_bfloat16 g_w2t_hi[(size_t)H * H];
__device__ __nv_bfloat16 g_w2t_lo[(size_t)H * H];
__device__ __nv_bfloat16 g_rw1t_hi[(size_t)H * 2 * H];
__device__ __nv_bfloat16 g_rw1t_lo[(size_t)H * 2 * H];

// ---------------- helpers ----------------
__device__ __forceinline__ void split_bf16(float v, __nv_bfloat16& hi, __nv_bfloat16& lo) {
    hi = __float2bfloat16(v);
    lo = __float2bfloat16(v - __bfloat162float(hi));
}
__device__ __forceinline__ uint16_t bf_bits(__nv_bfloat16 h) {
    uint16_t b; memcpy(&b, &h, 2); return b;
}
__device__ __forceinline__ uint32_t smem_u32(const void* p) {
    return (uint32_t)__cvta_generic_to_shared(p);
}
__device__ __forceinline__ void cp_async16(uint32_t smem_dst, const void* gmem_src) {
    asm volatile("cp.async.cg.shared.global [%0], [%1], 16;" :: "r"(smem_dst), "l"(gmem_src) : "memory");
}
__device__ __forceinline__ void cp_commit() {
    asm volatile("cp.async.commit_group;" ::: "memory");
}
#define CP_WAIT(n) asm volatile("cp.async.wait_group %0;" :: "n"(n) : "memory")

__device__ __forceinline__ void mma16816(float* d, const uint32_t* a, const uint32_t* b) {
    asm volatile(
        "mma.sync.aligned.m16n8k16.row.col.f32.bf16.bf16.f32 "
        "{%0,%1,%2,%3},{%4,%5,%6,%7},{%8,%9},{%0,%1,%2,%3};"
        : "+f"(d[0]), "+f"(d[1]), "+f"(d[2]), "+f"(d[3])
        : "r"(a[0]), "r"(a[1]), "r"(a[2]), "r"(a[3]), "r"(b[0]), "r"(b[1]));
}

// ---------------- concat -> bf16 hi/lo ----------------
__global__ void concat_kernel(const float* __restrict__ s,
                              const float* __restrict__ p,
                              const float* __restrict__ o) {
    size_t idx = (size_t)blockIdx.x * blockDim.x + threadIdx.x;   // float4 index
    size_t total = (size_t)NROWS * 3 * H / 4;
    if (idx >= total) return;
    size_t row = idx / (3 * H / 4);
    size_t col4 = idx % (3 * H / 4);
    const float4* src;
    size_t within;
    if (col4 < H / 4)            { src = (const float4*)s; within = col4; }
    else if (col4 < 2 * (H / 4)) { src = (const float4*)p; within = col4 - H / 4; }
    else                         { src = (const float4*)o; within = col4 - 2 * (H / 4); }
    float4 v = src[row * (H / 4) + within];
    __nv_bfloat16 h0, l0, h1, l1, h2v, l2, h3, l3;
    split_bf16(v.x, h0, l0); split_bf16(v.y, h1, l1);
    split_bf16(v.z, h2v, l2); split_bf16(v.w, h3, l3);
    uint32_t* dh = (uint32_t*)(g_vcat_hi + idx * 4);
    uint32_t* dl = (uint32_t*)(g_vcat_lo + idx * 4);
    dh[0] = (uint32_t)bf_bits(h0) | ((uint32_t)bf_bits(h1) << 16);
    dh[1] = (uint32_t)bf_bits(h2v) | ((uint32_t)bf_bits(h3) << 16);
    dl[0] = (uint32_t)bf_bits(l0) | ((uint32_t)bf_bits(l1) << 16);
    dl[1] = (uint32_t)bf_bits(l2) | ((uint32_t)bf_bits(l3) << 16);
}

// ---------------- weight transpose + split: W[K,N] f32 -> T[N,K] bf16 hi/lo ----------------
__global__ void wtrans_kernel(const float* __restrict__ W,
                              __nv_bfloat16* __restrict__ Thi,
                              __nv_bfloat16* __restrict__ Tlo,
                              int K, int N) {
    size_t idx = (size_t)blockIdx.x * blockDim.x + threadIdx.x;
    size_t total = (size_t)K * N;
    if (idx >= total) return;
    int n = (int)(idx / K);
    int k = (int)(idx % K);
    float v = W[(size_t)k * N + n];
    __nv_bfloat16 hi, lo;
    split_bf16(v, hi, lo);
    Thi[idx] = hi; Tlo[idx] = lo;
}

// ---------------- mma.sync bf16x3 GEMM ----------------
// C[M,Ntot] = act(A @ B^T + bias); A: [M,K] bf16 hi/lo, B: [Ntot,K] bf16 hi/lo.
// CTA: 256 thr, tile 128(M) x 128(N); warp tile 32x64; K chunks of 64, double buffered.
#define TG_LDS 72            // smem row stride in bf16 elements (144 B)
#define TG_ABYTES (128 * TG_LDS * 2)         // 18432 B per buffer
#define TG_SMEM  (4 * TG_ABYTES)             // A0,A1,B0,B1 = 73728 B

template<bool WB16, bool WF32, bool RELU>
__global__ __launch_bounds__(256, 2)
void tgemm_kernel(const __nv_bfloat16* __restrict__ Ahi, const __nv_bfloat16* __restrict__ Alo,
                  const __nv_bfloat16* __restrict__ Bhi, const __nv_bfloat16* __restrict__ Blo,
                  const float* __restrict__ bias,
                  __nv_bfloat16* __restrict__ Chi, __nv_bfloat16* __restrict__ Clo,
                  float* __restrict__ Cf32,
                  int K, int Ntot) {
    extern __shared__ __align__(16) __nv_bfloat16 smem[];
    __nv_bfloat16* Abuf[2] = {smem,                 smem + 128 * TG_LDS};
    __nv_bfloat16* Bbuf[2] = {smem + 2 * 128 * TG_LDS, smem + 3 * 128 * TG_LDS};

    const int tid = threadIdx.x;
    const int wid = tid >> 5;
    const int lane = tid & 31;
    const int g = lane >> 2;          // group id 0..7
    const int t = lane & 3;           // thread-in-group
    const int wm = wid & 3;           // warp row 0..3   (32 rows each)
    const int wn = wid >> 2;          // warp col 0..1   (64 cols each)
    const int bm = blockIdx.y * 128;
    const int bn = blockIdx.x * 128;

    const int per = K >> 6;           // 64-wide chunks per pass
    const int C = 3 * per;

    float acc[2][8][4];
#pragma unroll
    for (int i = 0; i < 2; i++)
#pragma unroll
        for (int j = 0; j < 8; j++)
#pragma unroll
            for (int q = 0; q < 4; q++) acc[i][j][q] = 0.f;

    auto load_chunk = [&](int c, int b) {
        int p = c / per;
        int kc = (c - p * per) << 6;
        const __nv_bfloat16* As = (p == 1) ? Alo : Ahi;
        const __nv_bfloat16* Bs = (p == 2) ? Blo : Bhi;
        uint32_t abase = smem_u32(Abuf[b]);
        uint32_t bbase = smem_u32(Bbuf[b]);
#pragma unroll
        for (int i = 0; i < 4; i++) {            // 1024 16B segs for A
            int seg = tid + i * 256;
            int row = seg >> 3, s = seg & 7;
            cp_async16(abase + (row * TG_LDS + s * 8) * 2,
                       As + (size_t)(bm + row) * K + kc + s * 8);
        }
#pragma unroll
        for (int i = 0; i < 4; i++) {            // 1024 16B segs for B
            int seg = tid + i * 256;
            int row = seg >> 3, s = seg & 7;
            cp_async16(bbase + (row * TG_LDS + s * 8) * 2,
                       Bs + (size_t)(bn + row) * K + kc + s * 8);
        }
    };

    load_chunk(0, 0); cp_commit();
    load_chunk(1, 1); cp_commit();

    for (int c = 0; c < C; c++) {
        const int b = c & 1;
        CP_WAIT(1);
        __syncthreads();

        const __nv_bfloat16* As = Abuf[b];
        const __nv_bfloat16* Bs = Bbuf[b];
#pragma unroll
        for (int ks = 0; ks < 4; ks++) {
            const int k0 = ks * 16;
            uint32_t afrag[2][4];
#pragma unroll
            for (int mt = 0; mt < 2; mt++) {
                int row = wm * 32 + mt * 16 + g;
                const __nv_bfloat16* ar0 = As + (size_t)row * TG_LDS + k0 + 2 * t;
                const __nv_bfloat16* ar1 = As + (size_t)(row + 8) * TG_LDS + k0 + 2 * t;
                afrag[mt][0] = *(const uint32_t*)ar0;
                afrag[mt][1] = *(const uint32_t*)ar1;
                afrag[mt][2] = *(const uint32_t*)(ar0 + 8);
                afrag[mt][3] = *(const uint32_t*)(ar1 + 8);
            }
#pragma unroll
            for (int nt = 0; nt < 8; nt++) {
                int n = wn * 64 + nt * 8 + g;
                const __nv_bfloat16* br = Bs + (size_t)n * TG_LDS + k0 + 2 * t;
                uint32_t bfrag[2];
                bfrag[0] = *(const uint32_t*)br;
                bfrag[1] = *(const uint32_t*)(br + 8);
#pragma unroll
                for (int mt = 0; mt < 2; mt++)
                    mma16816(acc[mt][nt], afrag[mt], bfrag);
            }
        }
        __syncthreads();
        if (c + 2 < C) load_chunk(c + 2, b);
        cp_commit();
    }

    // epilogue
#pragma unroll
    for (int mt = 0; mt < 2; mt++) {
        int row0 = bm + wm * 32 + mt * 16 + g;
        int row1 = row0 + 8;
#pragma unroll
        for (int nt = 0; nt < 8; nt++) {
            int col = bn + wn * 64 + nt * 8 + 2 * t;
            float2 bv = __ldg((const float2*)(bias + col));
            float v0 = acc[mt][nt][0] + bv.x;
            float v1 = acc[mt][nt][1] + bv.y;
            float v2 = acc[mt][nt][2] + bv.x;
            float v3 = acc[mt][nt][3] + bv.y;
            if (RELU) {
                v0 = fmaxf(v0, 0.f); v1 = fmaxf(v1, 0.f);
                v2 = fmaxf(v2, 0.f); v3 = fmaxf(v3, 0.f);
            }
            if (WF32) {
                *(float2*)(Cf32 + (size_t)row0 * Ntot + col) = make_float2(v0, v1);
                *(float2*)(Cf32 + (size_t)row1 * Ntot + col) = make_float2(v2, v3);
            }
            if (WB16) {
                __nv_bfloat16 h0, l0, h1, l1, h2v, l2, h3, l3;
                split_bf16(v0, h0, l0); split_bf16(v1, h1, l1);
                split_bf16(v2, h2v, l2); split_bf16(v3, h3, l3);
                *(uint32_t*)(Chi + (size_t)row0 * Ntot + col) =
                    (uint32_t)bf_bits(h0) | ((uint32_t)bf_bits(h1) << 16);
                *(uint32_t*)(Chi + (size_t)row1 * Ntot + col) =
                    (uint32_t)bf_bits(h2v) | ((uint32_t)bf_bits(h3) << 16);
                *(uint32_t*)(Clo + (size_t)row0 * Ntot + col) =
                    (uint32_t)bf_bits(l0) | ((uint32_t)bf_bits(l1) << 16);
                *(uint32_t*)(Clo + (size_t)row1 * Ntot + col) =
                    (uint32_t)bf_bits(l2) | ((uint32_t)bf_bits(l3) << 16);
            }
        }
    }
}

// ---------------- FFMA2 SGEMM (final N=69 GEMM) ----------------
__device__ __forceinline__ ull pack2(float lo, float hi) {
    ull r; asm("mov.b64 %0, {%1, %2};" : "=l"(r) : "f"(lo), "f"(hi)); return r;
}
__device__ __forceinline__ void unpack2(ull v, float& lo, float& hi) {
    asm("mov.b64 {%0, %1}, %2;" : "=f"(lo), "=f"(hi) : "l"(v));
}
__device__ __forceinline__ void fma2(ull& d, ull a, ull b) {
    asm("fma.rn.f32x2 %0, %1, %2, %3;" : "=l"(d) : "l"(a), "l"(b), "l"(d));
}

template<bool RELU>
__global__ __launch_bounds__(256)
void sgemm_kernel(const float* __restrict__ A, const float* __restrict__ B,
                  const float* __restrict__ bias, float* __restrict__ C,
                  int M, int Kd, int Nd) {
    __shared__ float As[8][132];
    __shared__ float Bs[8][128];

    const int bm = blockIdx.y * 128;
    const int bn = blockIdx.x * 128;
    const int tid = threadIdx.x;
    const int arow = tid >> 1;
    const int acol = (tid & 1) * 4;
    const int brow = tid >> 5;
    const int bcol = (tid & 31) * 4;
    const int tx = tid & 15;
    const int ty = tid >> 4;

    ull acc2[4][8];
#pragma unroll
    for (int i = 0; i < 4; i++)
#pragma unroll
        for (int j = 0; j < 8; j++) acc2[i][j] = 0ull;

    const bool full_n = (bn + 128 <= Nd);

    for (int k0 = 0; k0 < Kd; k0 += 8) {
        float4 a4 = *(const float4*)(A + (size_t)(bm + arow) * Kd + k0 + acol);
        As[acol + 0][arow] = a4.x;
        As[acol + 1][arow] = a4.y;
        As[acol + 2][arow] = a4.z;
        As[acol + 3][arow] = a4.w;
        if (full_n) {
            *(float4*)&Bs[brow][bcol] =
                *(const float4*)(B + (size_t)(k0 + brow) * Nd + bn + bcol);
        } else {
#pragma unroll
            for (int c = 0; c < 4; c++) {
                int col = bn + bcol + c;
                Bs[brow][bcol + c] = (col < Nd) ? B[(size_t)(k0 + brow) * Nd + col] : 0.f;
            }
        }
        __syncthreads();
#pragma unroll
        for (int k = 0; k < 8; k++) {
            ulonglong2 av0 = *(const ulonglong2*)&As[k][ty * 8];
            ulonglong2 av1 = *(const ulonglong2*)&As[k][ty * 8 + 4];
            ull a2[4] = {av0.x, av0.y, av1.x, av1.y};
            float4 blo = *(const float4*)&Bs[k][tx * 8];
            float4 bhi = *(const float4*)&Bs[k][tx * 8 + 4];
            ull b2[8];
            b2[0] = pack2(blo.x, blo.x); b2[1] = pack2(blo.y, blo.y);
            b2[2] = pack2(blo.z, blo.z); b2[3] = pack2(blo.w, blo.w);
            b2[4] = pack2(bhi.x, bhi.x); b2[5] = pack2(bhi.y, bhi.y);
            b2[6] = pack2(bhi.z, bhi.z); b2[7] = pack2(bhi.w, bhi.w);
#pragma unroll
            for (int i = 0; i < 4; i++)
#pragma unroll
                for (int j = 0; j < 8; j++)
                    fma2(acc2[i][j], a2[i], b2[j]);
        }
        __syncthreads();
    }
#pragma unroll
    for (int i = 0; i < 4; i++) {
        int row_lo = bm + ty * 8 + 2 * i;
        float* c0 = C + (size_t)row_lo * Nd;
        float* c1 = C + (size_t)(row_lo + 1) * Nd;
#pragma unroll
        for (int j = 0; j < 8; j++) {
            int col = bn + tx * 8 + j;
            if (col < Nd) {
                float lo, hi;
                unpack2(acc2[i][j], lo, hi);
                float bv = bias[col];
                lo += bv; hi += bv;
                if (RELU) { lo = fmaxf(lo, 0.f); hi = fmaxf(hi, 0.f); }
                c0[col] = lo;
                c1[col] = hi;
            }
        }
    }
}

// ---------------- fused attention (cp.async pipelined), writes rf hi/lo ----------------
__global__ __launch_bounds__(512)
void attn_kernel(const float* __restrict__ vf,
                 const float* __restrict__ rel_base,
                 const int* __restrict__ scats,
                 const int* __restrict__ ocats,
                 __nv_bfloat16* __restrict__ rf_hi,
                 __nv_bfloat16* __restrict__ rf_lo) {
    extern __shared__ float sm[];
    float* srel  = sm;                    // RR*H
    float* sdot  = srel + RR * H;
    float* ssq   = sdot + RR;
    float* sattn = ssq + RR;

    const int n = blockIdx.x;
    const int tid = threadIdx.x;
    const int lane = tid & 31;
    const int warp = tid >> 5;

    const int s = scats[n];
    const int o = ocats[n];
    const float* relp = rel_base + (((size_t)s * RR) * CC + o) * H;

    float4 vf4[4];
    const float4* vfn = (const float4*)(vf + (size_t)n * H);
#pragma unroll
    for (int it = 0; it < 4; it++) vf4[it] = __ldg(&vfn[lane + 32 * it]);

    const int T = (warp < (RR & 15)) ? (RR / 16 + 1) : (RR / 16);
    for (int t = 0; t < T; t++) {
        int r = warp + 16 * t;
        const float* src = relp + (size_t)r * CC * H;
        float* dst = srel + (size_t)r * H;
#pragma unroll
        for (int it = 0; it < 4; it++) {
            int j = lane + 32 * it;
            cp_async16(smem_u32(dst + 4 * j), src + 4 * j);
        }
        cp_commit();
    }

    for (int t = 0; t < T; t++) {
        switch (T - 1 - t) {
            case 0: CP_WAIT(0); break;
            case 1: CP_WAIT(1); break;
            case 2: CP_WAIT(2); break;
            case 3: CP_WAIT(3); break;
            default: CP_WAIT(4); break;
        }
        __syncwarp();
        int r = warp + 16 * t;
        const float4* rr4 = (const float4*)(srel + (size_t)r * H);
        float dot = 0.f, sq = 0.f;
#pragma unroll
        for (int it = 0; it < 4; it++) {
            float4 x = rr4[lane + 32 * it];
            float4 v = vf4[it];
            dot += x.x * v.x + x.y * v.y + x.z * v.z + x.w * v.w;
            sq  += x.x * x.x + x.y * x.y + x.z * x.z + x.w * x.w;
        }
#pragma unroll
        for (int off = 16; off > 0; off >>= 1) {
            dot += __shfl_down_sync(0xffffffffu, dot, off);
            sq  += __shfl_down_sync(0xffffffffu, sq, off);
        }
        if (lane == 0) { sdot[r] = dot; ssq[r] = sq; }
    }
    __syncthreads();

    if (warp == 0) {
        float vsq = 0.f;
#pragma unroll
        for (int it = 0; it < 4; it++) {
            float4 v = vf4[it];
            vsq += v.x * v.x + v.y * v.y + v.z * v.z + v.w * v.w;
        }
#pragma unroll
        for (int off = 16; off > 0; off >>= 1)
            vsq += __shfl_xor_sync(0xffffffffu, vsq, off);
        float vn = sqrtf(vsq);

        float c[3];
#pragma unroll
        for (int t = 0; t < 3; t++) {
            int r = lane + 32 * t;
            c[t] = (r < RR) ? sdot[r] / fmaxf(vn * sqrtf(ssq[r]), EPSV) : -1e30f;
        }
        float m = fmaxf(fmaxf(c[0], c[1]), c[2]);
#pragma unroll
        for (int off = 16; off > 0; off >>= 1)
            m = fmaxf(m, __shfl_xor_sync(0xffffffffu, m, off));
        float e[3], esum = 0.f;
#pragma unroll
        for (int t = 0; t < 3; t++) {
            int r = lane + 32 * t;
            e[t] = (r < RR) ? __expf(c[t] - m) : 0.f;
            esum += e[t];
        }
#pragma unroll
        for (int off = 16; off > 0; off >>= 1)
            esum += __shfl_xor_sync(0xffffffffu, esum, off);
        float inv = 1.f / esum;
#pragma unroll
        for (int t = 0; t < 3; t++) {
            int r = lane + 32 * t;
            if (r < RR) sattn[r] = e[t] * inv;
        }
    }
    __syncthreads();

    // attended + write rf = [vf | attended] as bf16 hi/lo
    {
        int d = tid;
        float acc = 0.f;
#pragma unroll 8
        for (int r = 0; r < RR; r++)
            acc = fmaf(sattn[r], srel[(size_t)r * H + d], acc);
        float vv = __ldg(vf + (size_t)n * H + d);
        __nv_bfloat16 h0, l0, h1, l1;
        split_bf16(vv, h0, l0);
        split_bf16(acc, h1, l1);
        size_t base = (size_t)n * 2 * H;
        rf_hi[base + d] = h0;      rf_lo[base + d] = l0;
        rf_hi[base + H + d] = h1;  rf_lo[base + H + d] = l1;
    }
}

// ---------------- launch ----------------
extern "C" void kernel_launch(void* const* d_in, const int* in_sizes, int n_in,
                              void* d_out, int out_size) {
    if (n_in < 14) return;
    const float* sfeat = (const float*)d_in[0];
    const float* pfeat = (const float*)d_in[1];
    const float* ofeat = (const float*)d_in[2];
    const float* rel   = (const float*)d_in[3];
    const float* w1    = (const float*)d_in[4];
    const float* b1    = (const float*)d_in[5];
    const float* w2    = (const float*)d_in[6];
    const float* b2    = (const float*)d_in[7];
    const float* rw1   = (const float*)d_in[8];
    const float* rb1   = (const float*)d_in[9];
    const float* rw2   = (const float*)d_in[10];
    const float* rb2   = (const float*)d_in[11];
    const int*   scats = (const int*)d_in[12];
    const int*   ocats = (const int*)d_in[13];
    float* out = (float*)d_out;

    __nv_bfloat16 *p_vcat_hi, *p_vcat_lo, *p_h_hi, *p_h_lo;
    __nv_bfloat16 *p_rf_hi, *p_rf_lo;
    __nv_bfloat16 *p_w1t_hi, *p_w1t_lo, *p_w2t_hi, *p_w2t_lo, *p_rw1t_hi, *p_rw1t_lo;
    float *p_vf, *p_h2;
    cudaGetSymbolAddress((void**)&p_vcat_hi, g_vcat_hi);
    cudaGetSymbolAddress((void**)&p_vcat_lo, g_vcat_lo);
    cudaGetSymbolAddress((void**)&p_h_hi, g_h_hi);
    cudaGetSymbolAddress((void**)&p_h_lo, g_h_lo);
    cudaGetSymbolAddress((void**)&p_vf, g_vf);
    cudaGetSymbolAddress((void**)&p_rf_hi, g_rf_hi);
    cudaGetSymbolAddress((void**)&p_rf_lo, g_rf_lo);
    cudaGetSymbolAddress((void**)&p_h2, g_h2);
    cudaGetSymbolAddress((void**)&p_w1t_hi, g_w1t_hi);
    cudaGetSymbolAddress((void**)&p_w1t_lo, g_w1t_lo);
    cudaGetSymbolAddress((void**)&p_w2t_hi, g_w2t_hi);
    cudaGetSymbolAddress((void**)&p_w2t_lo, g_w2t_lo);
    cudaGetSymbolAddress((void**)&p_rw1t_hi, g_rw1t_hi);
    cudaGetSymbolAddress((void**)&p_rw1t_lo, g_rw1t_lo);

    const int thr = 256;

    // 0) weight transpose + split
    wtrans_kernel<<<(int)(((size_t)3 * H * H + thr - 1) / thr), thr>>>(w1, p_w1t_hi, p_w1t_lo, 3 * H, H);
    wtrans_kernel<<<(int)(((size_t)H * H + thr - 1) / thr), thr>>>(w2, p_w2t_hi, p_w2t_lo, H, H);
    wtrans_kernel<<<(int)(((size_t)2 * H * H + thr - 1) / thr), thr>>>(rw1, p_rw1t_hi, p_rw1t_lo, 2 * H, H);

    // 1) concat -> vcat hi/lo
    {
        size_t total4 = (size_t)NROWS * 3 * H / 4;
        concat_kernel<<<(int)((total4 + thr - 1) / thr), thr>>>(sfeat, pfeat, ofeat);
    }
    // 2) h = relu(vcat @ w1 + b1)  -> bf16 hi/lo
    {
        cudaFuncSetAttribute(tgemm_kernel<true, false, true>,
                             cudaFuncAttributeMaxDynamicSharedMemorySize, TG_SMEM);
        dim3 grid(H / 128, NROWS / 128);
        tgemm_kernel<true, false, true><<<grid, 256, TG_SMEM>>>(
            p_vcat_hi, p_vcat_lo, p_w1t_hi, p_w1t_lo, b1,
            p_h_hi, p_h_lo, nullptr, 3 * H, H);
    }
    // 3) vf = relu(h @ w2 + b2)  -> f32
    {
        cudaFuncSetAttribute(tgemm_kernel<false, true, true>,
                             cudaFuncAttributeMaxDynamicSharedMemorySize, TG_SMEM);
        dim3 grid(H / 128, NROWS / 128);
        tgemm_kernel<false, true, true><<<grid, 256, TG_SMEM>>>(
            p_h_hi, p_h_lo, p_w2t_hi, p_w2t_lo, b2,
            nullptr, nullptr, p_vf, H, H);
    }
    // 4) attention -> rf hi/lo
    {
        int smem_bytes = (RR * H + 3 * RR) * (int)sizeof(float);
        cudaFuncSetAttribute(attn_kernel, cudaFuncAttributeMaxDynamicSharedMemorySize, smem_bytes);
        attn_kernel<<<NROWS, 512, smem_bytes>>>(p_vf, rel, scats, ocats, p_rf_hi, p_rf_lo);
    }
    // 5) h2 = relu(rf @ rw1 + rb1) -> f32
    {
        dim3 grid(H / 128, NROWS / 128);
        tgemm_kernel<false, true, true><<<grid, 256, TG_SMEM>>>(
            p_rf_hi, p_rf_lo, p_rw1t_hi, p_rw1t_lo, rb1,
            nullptr, nullptr, p_h2, 2 * H, H);
    }
    // 6) plogits = h2 @ rw2 + rb2   (FFMA2, Nd=69)
    {
        dim3 grid(1, NROWS / 128);
        sgemm_kernel<false><<<grid, 256>>>(p_h2, rw2, rb2, out, NROWS, H, PP);
    }
}

// round 6
// speedup vs baseline: 2.2550x; 1.1294x over previous
#include <cuda_runtime.h>
#include <cuda_bf16.h>
#include <math.h>
#include <stdint.h>
#include <string.h>

#define NROWS 8192
#define H 512
#define CC 100
#define RR 69
#define PP 69
#define EPSV 1e-8f

typedef unsigned long long ull;

// ---------------- scratch (device globals, no runtime alloc) ----------------
__device__ __nv_bfloat16 g_vcat_hi[(size_t)NROWS * 3 * H];
__device__ __nv_bfloat16 g_vcat_lo[(size_t)NROWS * 3 * H];
__device__ __nv_bfloat16 g_h_hi[(size_t)NROWS * H];
__device__ __nv_bfloat16 g_h_lo[(size_t)NROWS * H];
__device__ float         g_vf[(size_t)NROWS * H];
__device__ __nv_bfloat16 g_rf_hi[(size_t)NROWS * 2 * H];
__device__ __nv_bfloat16 g_rf_lo[(size_t)NROWS * 2 * H];
__device__ float         g_h2[(size_t)NROWS * H];
__device__ __nv_bfloat16 g_w1t_hi[(size_t)H * 3 * H];
__device__ __nv_bfloat16 g_w1t_lo[(size_t)H * 3 * H];
__device__ __nv_bfloat16 g_w2t_hi[(size_t)H * H];
__device__ __nv_bfloat16 g_w2t_lo[(size_t)H * H];
__device__ __nv_bfloat16 g_rw1t_hi[(size_t)H * 2 * H];
__device__ __nv_bfloat16 g_rw1t_lo[(size_t)H * 2 * H];

// ---------------- helpers ----------------
__device__ __forceinline__ void split_bf16(float v, __nv_bfloat16& hi, __nv_bfloat16& lo) {
    hi = __float2bfloat16(v);
    lo = __float2bfloat16(v - __bfloat162float(hi));
}
__device__ __forceinline__ uint16_t bf_bits(__nv_bfloat16 h) {
    uint16_t b; memcpy(&b, &h, 2); return b;
}
__device__ __forceinline__ uint32_t smem_u32(const void* p) {
    return (uint32_t)__cvta_generic_to_shared(p);
}
__device__ __forceinline__ void cp_async16(uint32_t smem_dst, const void* gmem_src) {
    asm volatile("cp.async.cg.shared.global [%0], [%1], 16;" :: "r"(smem_dst), "l"(gmem_src) : "memory");
}
__device__ __forceinline__ void cp_commit() {
    asm volatile("cp.async.commit_group;" ::: "memory");
}
#define CP_WAIT(n) asm volatile("cp.async.wait_group %0;" :: "n"(n) : "memory")

__device__ __forceinline__ void mma16816(float* d, const uint32_t* a, const uint32_t* b) {
    asm volatile(
        "mma.sync.aligned.m16n8k16.row.col.f32.bf16.bf16.f32 "
        "{%0,%1,%2,%3},{%4,%5,%6,%7},{%8,%9},{%0,%1,%2,%3};"
        : "+f"(d[0]), "+f"(d[1]), "+f"(d[2]), "+f"(d[3])
        : "r"(a[0]), "r"(a[1]), "r"(a[2]), "r"(a[3]), "r"(b[0]), "r"(b[1]));
}

// ---------------- concat -> bf16 hi/lo ----------------
__global__ void concat_kernel(const float* __restrict__ s,
                              const float* __restrict__ p,
                              const float* __restrict__ o) {
    size_t idx = (size_t)blockIdx.x * blockDim.x + threadIdx.x;
    size_t total = (size_t)NROWS * 3 * H / 4;
    if (idx >= total) return;
    size_t row = idx / (3 * H / 4);
    size_t col4 = idx % (3 * H / 4);
    const float4* src;
    size_t within;
    if (col4 < H / 4)            { src = (const float4*)s; within = col4; }
    else if (col4 < 2 * (H / 4)) { src = (const float4*)p; within = col4 - H / 4; }
    else                         { src = (const float4*)o; within = col4 - 2 * (H / 4); }
    float4 v = src[row * (H / 4) + within];
    __nv_bfloat16 h0, l0, h1, l1, h2v, l2, h3, l3;
    split_bf16(v.x, h0, l0); split_bf16(v.y, h1, l1);
    split_bf16(v.z, h2v, l2); split_bf16(v.w, h3, l3);
    uint32_t* dh = (uint32_t*)(g_vcat_hi + idx * 4);
    uint32_t* dl = (uint32_t*)(g_vcat_lo + idx * 4);
    dh[0] = (uint32_t)bf_bits(h0) | ((uint32_t)bf_bits(h1) << 16);
    dh[1] = (uint32_t)bf_bits(h2v) | ((uint32_t)bf_bits(h3) << 16);
    dl[0] = (uint32_t)bf_bits(l0) | ((uint32_t)bf_bits(l1) << 16);
    dl[1] = (uint32_t)bf_bits(l2) | ((uint32_t)bf_bits(l3) << 16);
}

// ---------------- weight transpose + split ----------------
__global__ void wtrans_kernel(const float* __restrict__ W,
                              __nv_bfloat16* __restrict__ Thi,
                              __nv_bfloat16* __restrict__ Tlo,
                              int K, int N) {
    size_t idx = (size_t)blockIdx.x * blockDim.x + threadIdx.x;
    size_t total = (size_t)K * N;
    if (idx >= total) return;
    int n = (int)(idx / K);
    int k = (int)(idx % K);
    float v = W[(size_t)k * N + n];
    __nv_bfloat16 hi, lo;
    split_bf16(v, hi, lo);
    Thi[idx] = hi; Tlo[idx] = lo;
}

// ---------------- mma.sync bf16x3 GEMM, 3-stage pipeline ----------------
#define TG_LDS 72
#define TG_STAGES 3
#define TG_STAGE_ELEMS (128 * TG_LDS)
#define TG_SMEM (2 * TG_STAGES * TG_STAGE_ELEMS * 2)   // 110592 B

template<bool WB16, bool WF32, bool RELU>
__global__ __launch_bounds__(256, 2)
void tgemm_kernel(const __nv_bfloat16* __restrict__ Ahi, const __nv_bfloat16* __restrict__ Alo,
                  const __nv_bfloat16* __restrict__ Bhi, const __nv_bfloat16* __restrict__ Blo,
                  const float* __restrict__ bias,
                  __nv_bfloat16* __restrict__ Chi, __nv_bfloat16* __restrict__ Clo,
                  float* __restrict__ Cf32,
                  int K, int Ntot) {
    extern __shared__ __align__(16) __nv_bfloat16 smem[];

    const int tid = threadIdx.x;
    const int wid = tid >> 5;
    const int lane = tid & 31;
    const int g = lane >> 2;
    const int t = lane & 3;
    const int wm = wid & 3;
    const int wn = wid >> 2;
    const int bm = blockIdx.y * 128;
    const int bn = blockIdx.x * 128;

    const int per = K >> 6;
    const int C = 3 * per;

    float acc[2][8][4];
#pragma unroll
    for (int i = 0; i < 2; i++)
#pragma unroll
        for (int j = 0; j < 8; j++)
#pragma unroll
            for (int q = 0; q < 4; q++) acc[i][j][q] = 0.f;

    auto load_chunk = [&](int c, int s) {
        int p = c / per;
        int kc = (c - p * per) << 6;
        const __nv_bfloat16* As = (p == 1) ? Alo : Ahi;
        const __nv_bfloat16* Bs = (p == 2) ? Blo : Bhi;
        uint32_t abase = smem_u32(smem + s * TG_STAGE_ELEMS);
        uint32_t bbase = smem_u32(smem + (TG_STAGES + s) * TG_STAGE_ELEMS);
#pragma unroll
        for (int i = 0; i < 4; i++) {
            int seg = tid + i * 256;
            int row = seg >> 3, sg = seg & 7;
            cp_async16(abase + (row * TG_LDS + sg * 8) * 2,
                       As + (size_t)(bm + row) * K + kc + sg * 8);
        }
#pragma unroll
        for (int i = 0; i < 4; i++) {
            int seg = tid + i * 256;
            int row = seg >> 3, sg = seg & 7;
            cp_async16(bbase + (row * TG_LDS + sg * 8) * 2,
                       Bs + (size_t)(bn + row) * K + kc + sg * 8);
        }
        cp_commit();
    };

    load_chunk(0, 0);
    load_chunk(1, 1);
    load_chunk(2, 2);

    for (int c = 0; c < C; c++) {
        const int s = c % TG_STAGES;
        CP_WAIT(2);                 // invariant: commits at entry = 3 + c
        __syncthreads();

        const __nv_bfloat16* As = smem + s * TG_STAGE_ELEMS;
        const __nv_bfloat16* Bs = smem + (TG_STAGES + s) * TG_STAGE_ELEMS;
#pragma unroll
        for (int ks = 0; ks < 4; ks++) {
            const int k0 = ks * 16;
            uint32_t afrag[2][4];
#pragma unroll
            for (int mt = 0; mt < 2; mt++) {
                int row = wm * 32 + mt * 16 + g;
                const __nv_bfloat16* ar0 = As + (size_t)row * TG_LDS + k0 + 2 * t;
                const __nv_bfloat16* ar1 = As + (size_t)(row + 8) * TG_LDS + k0 + 2 * t;
                afrag[mt][0] = *(const uint32_t*)ar0;
                afrag[mt][1] = *(const uint32_t*)ar1;
                afrag[mt][2] = *(const uint32_t*)(ar0 + 8);
                afrag[mt][3] = *(const uint32_t*)(ar1 + 8);
            }
#pragma unroll
            for (int nt = 0; nt < 8; nt++) {
                int n = wn * 64 + nt * 8 + g;
                const __nv_bfloat16* br = Bs + (size_t)n * TG_LDS + k0 + 2 * t;
                uint32_t bfrag[2];
                bfrag[0] = *(const uint32_t*)br;
                bfrag[1] = *(const uint32_t*)(br + 8);
#pragma unroll
                for (int mt = 0; mt < 2; mt++)
                    mma16816(acc[mt][nt], afrag[mt], bfrag);
            }
        }
        __syncthreads();
        if (c + 3 < C) load_chunk(c + 3, s);
        else cp_commit();           // keep commit-count invariant
    }

    // epilogue
#pragma unroll
    for (int mt = 0; mt < 2; mt++) {
        int row0 = bm + wm * 32 + mt * 16 + g;
        int row1 = row0 + 8;
#pragma unroll
        for (int nt = 0; nt < 8; nt++) {
            int col = bn + wn * 64 + nt * 8 + 2 * t;
            float2 bv = __ldg((const float2*)(bias + col));
            float v0 = acc[mt][nt][0] + bv.x;
            float v1 = acc[mt][nt][1] + bv.y;
            float v2 = acc[mt][nt][2] + bv.x;
            float v3 = acc[mt][nt][3] + bv.y;
            if (RELU) {
                v0 = fmaxf(v0, 0.f); v1 = fmaxf(v1, 0.f);
                v2 = fmaxf(v2, 0.f); v3 = fmaxf(v3, 0.f);
            }
            if (WF32) {
                *(float2*)(Cf32 + (size_t)row0 * Ntot + col) = make_float2(v0, v1);
                *(float2*)(Cf32 + (size_t)row1 * Ntot + col) = make_float2(v2, v3);
            }
            if (WB16) {
                __nv_bfloat16 h0, l0, h1, l1, h2v, l2, h3, l3;
                split_bf16(v0, h0, l0); split_bf16(v1, h1, l1);
                split_bf16(v2, h2v, l2); split_bf16(v3, h3, l3);
                *(uint32_t*)(Chi + (size_t)row0 * Ntot + col) =
                    (uint32_t)bf_bits(h0) | ((uint32_t)bf_bits(h1) << 16);
                *(uint32_t*)(Chi + (size_t)row1 * Ntot + col) =
                    (uint32_t)bf_bits(h2v) | ((uint32_t)bf_bits(h3) << 16);
                *(uint32_t*)(Clo + (size_t)row0 * Ntot + col) =
                    (uint32_t)bf_bits(l0) | ((uint32_t)bf_bits(l1) << 16);
                *(uint32_t*)(Clo + (size_t)row1 * Ntot + col) =
                    (uint32_t)bf_bits(l2) | ((uint32_t)bf_bits(l3) << 16);
            }
        }
    }
}

// ---------------- FFMA2 SGEMM (final N=69 GEMM) ----------------
__device__ __forceinline__ ull pack2(float lo, float hi) {
    ull r; asm("mov.b64 %0, {%1, %2};" : "=l"(r) : "f"(lo), "f"(hi)); return r;
}
__device__ __forceinline__ void unpack2(ull v, float& lo, float& hi) {
    asm("mov.b64 {%0, %1}, %2;" : "=f"(lo), "=f"(hi) : "l"(v));
}
__device__ __forceinline__ void fma2(ull& d, ull a, ull b) {
    asm("fma.rn.f32x2 %0, %1, %2, %3;" : "=l"(d) : "l"(a), "l"(b), "l"(d));
}

template<bool RELU>
__global__ __launch_bounds__(256)
void sgemm_kernel(const float* __restrict__ A, const float* __restrict__ B,
                  const float* __restrict__ bias, float* __restrict__ C,
                  int M, int Kd, int Nd) {
    __shared__ float As[8][132];
    __shared__ float Bs[8][128];

    const int bm = blockIdx.y * 128;
    const int bn = blockIdx.x * 128;
    const int tid = threadIdx.x;
    const int arow = tid >> 1;
    const int acol = (tid & 1) * 4;
    const int brow = tid >> 5;
    const int bcol = (tid & 31) * 4;
    const int tx = tid & 15;
    const int ty = tid >> 4;

    ull acc2[4][8];
#pragma unroll
    for (int i = 0; i < 4; i++)
#pragma unroll
        for (int j = 0; j < 8; j++) acc2[i][j] = 0ull;

    const bool full_n = (bn + 128 <= Nd);

    for (int k0 = 0; k0 < Kd; k0 += 8) {
        float4 a4 = *(const float4*)(A + (size_t)(bm + arow) * Kd + k0 + acol);
        As[acol + 0][arow] = a4.x;
        As[acol + 1][arow] = a4.y;
        As[acol + 2][arow] = a4.z;
        As[acol + 3][arow] = a4.w;
        if (full_n) {
            *(float4*)&Bs[brow][bcol] =
                *(const float4*)(B + (size_t)(k0 + brow) * Nd + bn + bcol);
        } else {
#pragma unroll
            for (int c = 0; c < 4; c++) {
                int col = bn + bcol + c;
                Bs[brow][bcol + c] = (col < Nd) ? B[(size_t)(k0 + brow) * Nd + col] : 0.f;
            }
        }
        __syncthreads();
#pragma unroll
        for (int k = 0; k < 8; k++) {
            ulonglong2 av0 = *(const ulonglong2*)&As[k][ty * 8];
            ulonglong2 av1 = *(const ulonglong2*)&As[k][ty * 8 + 4];
            ull a2[4] = {av0.x, av0.y, av1.x, av1.y};
            float4 blo = *(const float4*)&Bs[k][tx * 8];
            float4 bhi = *(const float4*)&Bs[k][tx * 8 + 4];
            ull b2[8];
            b2[0] = pack2(blo.x, blo.x); b2[1] = pack2(blo.y, blo.y);
            b2[2] = pack2(blo.z, blo.z); b2[3] = pack2(blo.w, blo.w);
            b2[4] = pack2(bhi.x, bhi.x); b2[5] = pack2(bhi.y, bhi.y);
            b2[6] = pack2(bhi.z, bhi.z); b2[7] = pack2(bhi.w, bhi.w);
#pragma unroll
            for (int i = 0; i < 4; i++)
#pragma unroll
                for (int j = 0; j < 8; j++)
                    fma2(acc2[i][j], a2[i], b2[j]);
        }
        __syncthreads();
    }
#pragma unroll
    for (int i = 0; i < 4; i++) {
        int row_lo = bm + ty * 8 + 2 * i;
        float* c0 = C + (size_t)row_lo * Nd;
        float* c1 = C + (size_t)(row_lo + 1) * Nd;
#pragma unroll
        for (int j = 0; j < 8; j++) {
            int col = bn + tx * 8 + j;
            if (col < Nd) {
                float lo, hi;
                unpack2(acc2[i][j], lo, hi);
                float bv = bias[col];
                lo += bv; hi += bv;
                if (RELU) { lo = fmaxf(lo, 0.f); hi = fmaxf(hi, 0.f); }
                c0[col] = lo;
                c1[col] = hi;
            }
        }
    }
}

// ---------------- streaming online-softmax attention ----------------
// CTA = one row n, 256 threads; rel streamed in 8-row chunks via 3-stage cp.async ring.
#define ACH 8
#define ASTAGES 3
#define A_SMEM ((ASTAGES * ACH * H + H + 4 * ACH + 8) * 4)   // floats*4 bytes

__global__ __launch_bounds__(256)
void attn_kernel(const float* __restrict__ vf,
                 const float* __restrict__ rel_base,
                 const int* __restrict__ scats,
                 const int* __restrict__ ocats,
                 __nv_bfloat16* __restrict__ rf_hi,
                 __nv_bfloat16* __restrict__ rf_lo) {
    extern __shared__ float sm[];
    float* ring  = sm;                                 // ASTAGES*ACH*H
    float* svf   = ring + ASTAGES * ACH * H;           // H
    float* sdot  = svf + H;                            // ACH
    float* ssq   = sdot + ACH;                         // ACH
    float* sw    = ssq + ACH;                          // ACH
    float* sred  = sw + ACH;                           // 8 (vn partials)
    float* sstat = sred + 8;                           // [0]=scale [1]=s_run

    const int n = blockIdx.x;
    const int tid = threadIdx.x;
    const int lane = tid & 31;
    const int warp = tid >> 5;

    const int s = scats[n];
    const int o = ocats[n];
    const float* relp = rel_base + (((size_t)s * RR) * CC + o) * H;

    auto load_chunk = [&](int tc) {
        float* dst = ring + (tc % ASTAGES) * (ACH * H);
#pragma unroll
        for (int i = 0; i < 4; i++) {
            int idx = tid + i * 256;       // float4 index, 0..1023
            int j = idx >> 7;              // row within chunk
            int col4 = idx & 127;
            int r = tc * ACH + j;
            if (r < RR)
                cp_async16(smem_u32(dst + j * H + col4 * 4),
                           relp + (size_t)r * CC * H + col4 * 4);
        }
        cp_commit();
    };

    // vf into smem
    if (tid < 128)
        ((float4*)svf)[tid] = __ldg(&((const float4*)(vf + (size_t)n * H))[tid]);

    load_chunk(0);
    load_chunk(1);
    load_chunk(2);

    // vn partials (needs svf; visible to this thread since it wrote/will read after sync)
    __syncthreads();
    {
        float v0 = svf[tid], v1 = svf[tid + 256];
        float part = v0 * v0 + v1 * v1;
#pragma unroll
        for (int off = 16; off > 0; off >>= 1)
            part += __shfl_xor_sync(0xffffffffu, part, off);
        if (lane == 0) sred[warp] = part;
    }

    const int chunks = (RR + ACH - 1) / ACH;   // 9
    float acc0 = 0.f, acc1 = 0.f;
    float m_run = -1e30f, s_run = 0.f, vn = 0.f;   // m_run/s_run/vn live in warp 0

    for (int tc = 0; tc < chunks; tc++) {
        CP_WAIT(2);                 // commits at entry = 3 + tc (tail always commits)
        __syncthreads();            // chunk tc visible to all; also sred (tc==0)

        // dots: warp w -> chunk row w
        {
            const float4* cb4 = (const float4*)(ring + (tc % ASTAGES) * (ACH * H) + warp * H);
            const float4* vf4s = (const float4*)svf;
            float dot = 0.f, sq = 0.f;
#pragma unroll
            for (int i = 0; i < 4; i++) {
                float4 x = cb4[lane + 32 * i];
                float4 v = vf4s[lane + 32 * i];
                dot += x.x * v.x + x.y * v.y + x.z * v.z + x.w * v.w;
                sq  += x.x * x.x + x.y * x.y + x.z * x.z + x.w * x.w;
            }
#pragma unroll
            for (int off = 16; off > 0; off >>= 1) {
                dot += __shfl_down_sync(0xffffffffu, dot, off);
                sq  += __shfl_down_sync(0xffffffffu, sq, off);
            }
            if (lane == 0) { sdot[warp] = dot; ssq[warp] = sq; }
        }
        __syncthreads();

        // warp 0: online softmax update
        if (warp == 0) {
            if (tc == 0) {
                float vsq = (lane < 8) ? sred[lane] : 0.f;
#pragma unroll
                for (int off = 4; off > 0; off >>= 1)
                    vsq += __shfl_xor_sync(0xffffffffu, vsq, off);
                vsq = __shfl_sync(0xffffffffu, vsq, 0);
                vn = sqrtf(vsq);
            }
            int r = tc * ACH + lane;
            float c = -1e30f;
            if (lane < ACH && r < RR)
                c = sdot[lane] / fmaxf(vn * sqrtf(ssq[lane]), EPSV);
            float mc = c;
#pragma unroll
            for (int off = 16; off > 0; off >>= 1)
                mc = fmaxf(mc, __shfl_xor_sync(0xffffffffu, mc, off));
            float m_new = fmaxf(m_run, mc);
            float w = (lane < ACH) ? __expf(c - m_new) : 0.f;
            float wsum = w;
#pragma unroll
            for (int off = 16; off > 0; off >>= 1)
                wsum += __shfl_xor_sync(0xffffffffu, wsum, off);
            float scale = __expf(m_run - m_new);
            s_run = s_run * scale + wsum;
            m_run = m_new;
            if (lane < ACH) sw[lane] = w;
            if (lane == 0) sstat[0] = scale;
            if (lane == 0 && tc == chunks - 1) sstat[1] = s_run;
        }
        __syncthreads();

        // all threads: rescale + accumulate
        {
            float scale = sstat[0];
            acc0 *= scale; acc1 *= scale;
            const float* cb = ring + (tc % ASTAGES) * (ACH * H);
#pragma unroll
            for (int r = 0; r < ACH; r++) {
                float wr = sw[r];
                acc0 = fmaf(wr, cb[r * H + tid], acc0);
                acc1 = fmaf(wr, cb[r * H + tid + 256], acc1);
            }
        }
        __syncthreads();            // buffer reusable

        if (tc + 3 < chunks) load_chunk(tc + 3);
        else cp_commit();
    }

    // finalize
    float inv = 1.f / sstat[1];
    float att0 = acc0 * inv, att1 = acc1 * inv;
    float vv0 = svf[tid], vv1 = svf[tid + 256];

    __nv_bfloat16 h, l;
    size_t base = (size_t)n * 2 * H;
    split_bf16(vv0, h, l);  rf_hi[base + tid] = h;          rf_lo[base + tid] = l;
    split_bf16(vv1, h, l);  rf_hi[base + tid + 256] = h;    rf_lo[base + tid + 256] = l;
    split_bf16(att0, h, l); rf_hi[base + H + tid] = h;      rf_lo[base + H + tid] = l;
    split_bf16(att1, h, l); rf_hi[base + H + tid + 256] = h; rf_lo[base + H + tid + 256] = l;
}

// ---------------- launch ----------------
extern "C" void kernel_launch(void* const* d_in, const int* in_sizes, int n_in,
                              void* d_out, int out_size) {
    if (n_in < 14) return;
    const float* sfeat = (const float*)d_in[0];
    const float* pfeat = (const float*)d_in[1];
    const float* ofeat = (const float*)d_in[2];
    const float* rel   = (const float*)d_in[3];
    const float* w1    = (const float*)d_in[4];
    const float* b1    = (const float*)d_in[5];
    const float* w2    = (const float*)d_in[6];
    const float* b2    = (const float*)d_in[7];
    const float* rw1   = (const float*)d_in[8];
    const float* rb1   = (const float*)d_in[9];
    const float* rw2   = (const float*)d_in[10];
    const float* rb2   = (const float*)d_in[11];
    const int*   scats = (const int*)d_in[12];
    const int*   ocats = (const int*)d_in[13];
    float* out = (float*)d_out;

    __nv_bfloat16 *p_vcat_hi, *p_vcat_lo, *p_h_hi, *p_h_lo;
    __nv_bfloat16 *p_rf_hi, *p_rf_lo;
    __nv_bfloat16 *p_w1t_hi, *p_w1t_lo, *p_w2t_hi, *p_w2t_lo, *p_rw1t_hi, *p_rw1t_lo;
    float *p_vf, *p_h2;
    cudaGetSymbolAddress((void**)&p_vcat_hi, g_vcat_hi);
    cudaGetSymbolAddress((void**)&p_vcat_lo, g_vcat_lo);
    cudaGetSymbolAddress((void**)&p_h_hi, g_h_hi);
    cudaGetSymbolAddress((void**)&p_h_lo, g_h_lo);
    cudaGetSymbolAddress((void**)&p_vf, g_vf);
    cudaGetSymbolAddress((void**)&p_rf_hi, g_rf_hi);
    cudaGetSymbolAddress((void**)&p_rf_lo, g_rf_lo);
    cudaGetSymbolAddress((void**)&p_h2, g_h2);
    cudaGetSymbolAddress((void**)&p_w1t_hi, g_w1t_hi);
    cudaGetSymbolAddress((void**)&p_w1t_lo, g_w1t_lo);
    cudaGetSymbolAddress((void**)&p_w2t_hi, g_w2t_hi);
    cudaGetSymbolAddress((void**)&p_w2t_lo, g_w2t_lo);
    cudaGetSymbolAddress((void**)&p_rw1t_hi, g_rw1t_hi);
    cudaGetSymbolAddress((void**)&p_rw1t_lo, g_rw1t_lo);

    const int thr = 256;

    // 0) weight transpose + split
    wtrans_kernel<<<(int)(((size_t)3 * H * H + thr - 1) / thr), thr>>>(w1, p_w1t_hi, p_w1t_lo, 3 * H, H);
    wtrans_kernel<<<(int)(((size_t)H * H + thr - 1) / thr), thr>>>(w2, p_w2t_hi, p_w2t_lo, H, H);
    wtrans_kernel<<<(int)(((size_t)2 * H * H + thr - 1) / thr), thr>>>(rw1, p_rw1t_hi, p_rw1t_lo, 2 * H, H);

    // 1) concat -> vcat hi/lo
    {
        size_t total4 = (size_t)NROWS * 3 * H / 4;
        concat_kernel<<<(int)((total4 + thr - 1) / thr), thr>>>(sfeat, pfeat, ofeat);
    }
    // 2) h = relu(vcat @ w1 + b1)  -> bf16 hi/lo
    {
        cudaFuncSetAttribute(tgemm_kernel<true, false, true>,
                             cudaFuncAttributeMaxDynamicSharedMemorySize, TG_SMEM);
        dim3 grid(H / 128, NROWS / 128);
        tgemm_kernel<true, false, true><<<grid, 256, TG_SMEM>>>(
            p_vcat_hi, p_vcat_lo, p_w1t_hi, p_w1t_lo, b1,
            p_h_hi, p_h_lo, nullptr, 3 * H, H);
    }
    // 3) vf = relu(h @ w2 + b2)  -> f32
    {
        cudaFuncSetAttribute(tgemm_kernel<false, true, true>,
                             cudaFuncAttributeMaxDynamicSharedMemorySize, TG_SMEM);
        dim3 grid(H / 128, NROWS / 128);
        tgemm_kernel<false, true, true><<<grid, 256, TG_SMEM>>>(
            p_h_hi, p_h_lo, p_w2t_hi, p_w2t_lo, b2,
            nullptr, nullptr, p_vf, H, H);
    }
    // 4) streaming attention -> rf hi/lo
    {
        cudaFuncSetAttribute(attn_kernel, cudaFuncAttributeMaxDynamicSharedMemorySize, A_SMEM);
        attn_kernel<<<NROWS, 256, A_SMEM>>>(p_vf, rel, scats, ocats, p_rf_hi, p_rf_lo);
    }
    // 5) h2 = relu(rf @ rw1 + rb1) -> f32
    {
        dim3 grid(H / 128, NROWS / 128);
        tgemm_kernel<false, true, true><<<grid, 256, TG_SMEM>>>(
            p_rf_hi, p_rf_lo, p_rw1t_hi, p_rw1t_lo, rb1,
            nullptr, nullptr, p_h2, 2 * H, H);
    }
    // 6) plogits = h2 @ rw2 + rb2   (FFMA2, Nd=69)
    {
        dim3 grid(1, NROWS / 128);
        sgemm_kernel<false><<<grid, 256>>>(p_h2, rw2, rb2, out, NROWS, H, PP);
    }
}